// round 2
// baseline (speedup 1.0000x reference)
#include <cuda_runtime.h>
#include <cuda_fp16.h>
#include <cstdint>

// Problem dims
#define M_DIM 8192
#define N_DIM 4096
#define K_DIM 4096

// GEMM tiling
#define BM 128
#define BN 128
#define BK 64                         // halves per k-chunk (128 bytes per row)
#define KITERS (K_DIM / BK)           // 64
#define STAGES 3
#define SLAB_BYTES 16384              // 128 rows x 128B SW128-swizzled slab
#define STAGE_BYTES (2 * SLAB_BYTES)  // A slab + B slab = 32KB
#define SMEM_ALLOC (STAGES * STAGE_BYTES)

// Staging buffers in device globals (no runtime allocation allowed).
// Stored PRE-SWIZZLED (SW128 XOR applied) in tiled layout: tile(t, kt) is a
// contiguous 16KB slab of 128 rows x 128 bytes. cp.async then copies bytes
// linearly and ldmatrix reads conflict-free with the same XOR addressing.
__device__ __align__(256) __half g_xh[(size_t)M_DIM * K_DIM];
__device__ __align__(256) __half g_wh[(size_t)N_DIM * K_DIM];

// ---------------------------------------------------------------------------
// Helpers
// ---------------------------------------------------------------------------
__device__ __forceinline__ uint32_t smem_u32(const void* p) {
    uint32_t a;
    asm("{ .reg .u64 t; cvta.to.shared.u64 t, %1; cvt.u32.u64 %0, t; }"
        : "=r"(a) : "l"(p));
    return a;
}

__device__ __forceinline__ void cp16(uint32_t dst, const void* src) {
    asm volatile("cp.async.cg.shared.global [%0], [%1], 16;"
                 :: "r"(dst), "l"(src) : "memory");
}
#define CP_COMMIT() asm volatile("cp.async.commit_group;" ::: "memory")
#define CP_WAIT2()  asm volatile("cp.async.wait_group 2;" ::: "memory")

#define LDSM4(r, addr)                                                         \
    asm volatile("ldmatrix.sync.aligned.m8n8.x4.shared.b16 {%0,%1,%2,%3}, [%4];" \
                 : "=r"((r)[0]), "=r"((r)[1]), "=r"((r)[2]), "=r"((r)[3])      \
                 : "r"(addr))

#define MMA16816(c, a, b0v, b1v)                                               \
    asm volatile("mma.sync.aligned.m16n8k16.row.col.f32.f16.f16.f32 "          \
                 "{%0,%1,%2,%3}, {%4,%5,%6,%7}, {%8,%9}, {%0,%1,%2,%3};"       \
                 : "+f"((c)[0]), "+f"((c)[1]), "+f"((c)[2]), "+f"((c)[3])      \
                 : "r"((a)[0]), "r"((a)[1]), "r"((a)[2]), "r"((a)[3]),         \
                   "r"(b0v), "r"(b1v))

__device__ __forceinline__ uint32_t sw128(uint32_t off) {
    return off ^ ((off >> 3) & 0x70);
}
__device__ __forceinline__ uint32_t h2_bits(__half2 h) {
    return *reinterpret_cast<uint32_t*>(&h);
}

// ---------------------------------------------------------------------------
// Stage 0: x fp32 -> fp16, swizzled tiled layout
// ---------------------------------------------------------------------------
__global__ __launch_bounds__(256) void k_convert_x(const float* __restrict__ x) {
    size_t idx = (size_t)blockIdx.x * blockDim.x + threadIdx.x;  // one float4
    if (idx >= (size_t)M_DIM * K_DIM / 4) return;
    int m  = (int)(idx >> 10);       // K/4 = 1024 float4 per row
    int k  = (int)(idx & 1023) << 2;

    float4 v = reinterpret_cast<const float4*>(x)[idx];
    uint2 u;
    u.x = h2_bits(__floats2half2_rn(v.x, v.y));
    u.y = h2_bits(__floats2half2_rn(v.z, v.w));

    int mt = m >> 7, r = m & 127, kt = k >> 6, c = k & 63;
    size_t base = ((size_t)(mt * (K_DIM / 64) + kt)) << 14;
    uint32_t off = sw128((uint32_t)(r * 128 + c * 2));
    *reinterpret_cast<uint2*>(reinterpret_cast<char*>(g_xh) + base + off) = u;
}

// ---------------------------------------------------------------------------
// Stage 1: int4 dequant -> fp16, swizzled tiled layout
// element e of word p = ((int)(w << 4e)) >> 28  (sign extended)
// ---------------------------------------------------------------------------
__global__ __launch_bounds__(256) void k_dequant_w(const int* __restrict__ pw,
                                                   const float* __restrict__ scale) {
    int idx = blockIdx.x * blockDim.x + threadIdx.x;  // one int32 word
    if (idx >= N_DIM * (K_DIM / 8)) return;
    int o = idx >> 9;    // 512 words per output row
    int p = idx & 511;

    int w = pw[idx];
    float s = scale[(o << 5) + (p >> 4)];  // group = (p*8)/128 = p/16

    float f[8];
#pragma unroll
    for (int e = 0; e < 8; e++) {
        int v = ((int)((unsigned)w << (4 * e))) >> 28;
        f[e] = (float)v * s;
    }
    uint4 u;
    u.x = h2_bits(__floats2half2_rn(f[0], f[1]));
    u.y = h2_bits(__floats2half2_rn(f[2], f[3]));
    u.z = h2_bits(__floats2half2_rn(f[4], f[5]));
    u.w = h2_bits(__floats2half2_rn(f[6], f[7]));

    int nt = o >> 7, r = o & 127, kt = p >> 3, cb = (p & 7) * 16;
    size_t base = ((size_t)(nt * (K_DIM / 64) + kt)) << 14;
    uint32_t off = sw128((uint32_t)(r * 128 + cb));
    *reinterpret_cast<uint4*>(reinterpret_cast<char*>(g_wh) + base + off) = u;
}

// ---------------------------------------------------------------------------
// Stage 2: fp16 HMMA GEMM (mma.sync m16n8k16, fp32 accum) + bias epilogue
// 256 threads = 8 warps, warp grid 4(M) x 2(N), warp tile 32x64.
// 3-stage cp.async pipeline, 32KB/stage.
// ---------------------------------------------------------------------------
__global__ __launch_bounds__(256, 2) void k_gemm(const float* __restrict__ bias,
                                                 float* __restrict__ out) {
    extern __shared__ __align__(1024) char smem[];
    const uint32_t sb = smem_u32(smem);
    const int tid  = threadIdx.x;
    const int wid  = tid >> 5, lane = tid & 31;
    const int wm   = wid & 3,  wn   = wid >> 2;

    const int nt = blockIdx.x, mt = blockIdx.y;
    const char* aG = reinterpret_cast<const char*>(g_xh) +
                     (size_t)mt * (K_DIM / 64) * SLAB_BYTES;
    const char* bG = reinterpret_cast<const char*>(g_wh) +
                     (size_t)nt * (K_DIM / 64) * SLAB_BYTES;

    float acc[2][8][4];
#pragma unroll
    for (int i = 0; i < 2; i++)
#pragma unroll
        for (int j = 0; j < 8; j++)
#pragma unroll
            for (int q = 0; q < 4; q++) acc[i][j][q] = 0.f;

    // ldmatrix lane addressing: matrix id g = lane/8, row-in-matrix lr = lane%8
    const int g  = lane >> 3;
    const int lr = lane & 7;

    // Prologue: fill all stages
#pragma unroll
    for (int s = 0; s < STAGES; s++) {
        const uint32_t dA = sb + s * STAGE_BYTES;
        const char* srcA = aG + (size_t)s * SLAB_BYTES;
        const char* srcB = bG + (size_t)s * SLAB_BYTES;
#pragma unroll
        for (int j = 0; j < 4; j++) {
            const uint32_t o = (uint32_t)(tid + j * 256) * 16;
            cp16(dA + o,              srcA + o);
            cp16(dA + SLAB_BYTES + o, srcB + o);
        }
        CP_COMMIT();
    }

    int slot = 0;
    for (int it = 0; it < KITERS; it++) {
        CP_WAIT2();
        __syncthreads();
        const uint32_t sA = sb + slot * STAGE_BYTES;
        const uint32_t sB = sA + SLAB_BYTES;

#pragma unroll
        for (int ks = 0; ks < 4; ks++) {
            const uint32_t colb = (uint32_t)((ks * 16 + (g >> 1) * 8) * 2);

            uint32_t a[2][4];
#pragma unroll
            for (int sm = 0; sm < 2; sm++) {
                const uint32_t row = (uint32_t)(wm * 32 + sm * 16 + (g & 1) * 8 + lr);
                const uint32_t o = row * 128 + colb;
                LDSM4(a[sm], sA + (o ^ ((o >> 3) & 0x70)));
            }
            uint32_t bb[4][4];
#pragma unroll
            for (int ns = 0; ns < 4; ns++) {
                const uint32_t row = (uint32_t)(wn * 64 + ns * 16 + (g & 1) * 8 + lr);
                const uint32_t o = row * 128 + colb;
                LDSM4(bb[ns], sB + (o ^ ((o >> 3) & 0x70)));
            }
#pragma unroll
            for (int sm = 0; sm < 2; sm++)
#pragma unroll
                for (int j = 0; j < 8; j++)
                    MMA16816(acc[sm][j], a[sm], bb[j >> 1][j & 1],
                             bb[j >> 1][(j & 1) + 2]);
        }
        __syncthreads();

        const int nit = it + STAGES;
        if (nit < KITERS) {
            const uint32_t dA = sb + slot * STAGE_BYTES;
            const char* srcA = aG + (size_t)nit * SLAB_BYTES;
            const char* srcB = bG + (size_t)nit * SLAB_BYTES;
#pragma unroll
            for (int j = 0; j < 4; j++) {
                const uint32_t o = (uint32_t)(tid + j * 256) * 16;
                cp16(dA + o,              srcA + o);
                cp16(dA + SLAB_BYTES + o, srcB + o);
            }
        }
        CP_COMMIT();  // unconditional: keeps group accounting exact at the tail
        if (++slot == STAGES) slot = 0;
    }

    // Epilogue: bias add + float2 stores (32B-coalesced per quad)
    const int qrow = lane >> 2;
    const int qcol = (lane & 3) * 2;
    const size_t obase = (size_t)(mt * BM) * N_DIM + (size_t)(nt * BN);

#pragma unroll
    for (int sm = 0; sm < 2; sm++) {
        const int r0 = wm * 32 + sm * 16 + qrow;
#pragma unroll
        for (int j = 0; j < 8; j++) {
            const int c0 = wn * 64 + j * 8 + qcol;
            const float b0 = __ldg(bias + nt * BN + c0);
            const float b1 = __ldg(bias + nt * BN + c0 + 1);
            float2 v0 = make_float2(acc[sm][j][0] + b0, acc[sm][j][1] + b1);
            float2 v1 = make_float2(acc[sm][j][2] + b0, acc[sm][j][3] + b1);
            *reinterpret_cast<float2*>(out + obase + (size_t)r0 * N_DIM + c0) = v0;
            *reinterpret_cast<float2*>(out + obase + (size_t)(r0 + 8) * N_DIM + c0) = v1;
        }
    }
}

// ---------------------------------------------------------------------------
// Launch
// ---------------------------------------------------------------------------
extern "C" void kernel_launch(void* const* d_in, const int* in_sizes, int n_in,
                              void* d_out, int out_size) {
    const float* x     = (const float*)d_in[0];
    const int*   pw    = (const int*)d_in[1];
    const float* scale = (const float*)d_in[2];
    const float* bias  = (const float*)d_in[3];
    float*       out   = (float*)d_out;

    (void)in_sizes; (void)n_in; (void)out_size;

    k_convert_x<<<32768, 256>>>(x);
    k_dequant_w<<<8192, 256>>>(pw, scale);

    cudaFuncSetAttribute(k_gemm, cudaFuncAttributeMaxDynamicSharedMemorySize,
                         SMEM_ALLOC);
    dim3 grid(N_DIM / BN, M_DIM / BM);
    k_gemm<<<grid, 256, SMEM_ALLOC>>>(bias, out);
}